// round 10
// baseline (speedup 1.0000x reference)
#include <cuda_runtime.h>
#include <cuda_fp16.h>

// L1AttnSparse — GB300 sm_103a, round 10: 2 tokens per warp for dual
// independent dependency chains (latency hiding via ILP, not occupancy).
// bs=2, n_tok=2048, n_heads=8, width=64, deg=32
// Warp = head; 8 lanes per edge; interleaved fp16 KV staging buffer
// (k at [0], v at +1024B). HFMA2 phase-4 accumulation with even/odd split.

#define BS   2
#define NTOK 2048
#define NH   8
#define WID  64
#define DEG  32
#define ROW  (NH * WID)            // 512 floats per token row
#define TOT  (BS * NTOK * ROW)     // 2,097,152 elements per tensor
#define U4TOK 128                  // uint4 per interleaved token row (2048B)
#define SCALE (-0.125f)            // -1/sqrt(64)

typedef unsigned long long u64;

// interleaved: token n -> [n*2048, +1024) = k row fp16, [+1024, +2048) = v row
__device__ __half2 g_kv[TOT];      // 8MB

__device__ __forceinline__ u64 pack2(float lo, float hi) {
    u64 r;
    asm("mov.b64 %0, {%1, %2};" : "=l"(r) : "f"(lo), "f"(hi));
    return r;
}
__device__ __forceinline__ float2 unpack2(u64 p) {
    float2 f;
    asm("mov.b64 {%0, %1}, %2;" : "=f"(f.x), "=f"(f.y) : "l"(p));
    return f;
}
__device__ __forceinline__ u64 add2(u64 a, u64 b) {
    u64 r;
    asm("add.rn.f32x2 %0, %1, %2;" : "=l"(r) : "l"(a), "l"(b));
    return r;
}

__global__ __launch_bounds__(256)
void convert_kernel(const float* __restrict__ k, const float* __restrict__ v)
{
    const int i = blockIdx.x * blockDim.x + threadIdx.x;   // one float4 of k and v
    const int n   = i >> 7;            // token
    const int off = i & 127;           // uint2 slot within row
    const float4 kf = ((const float4*)k)[i];
    const float4 vf = ((const float4*)v)[i];
    union { __half2 h[2]; uint2 u; } pk, pv;
    pk.h[0] = __floats2half2_rn(kf.x, kf.y);
    pk.h[1] = __floats2half2_rn(kf.z, kf.w);
    pv.h[0] = __floats2half2_rn(vf.x, vf.y);
    pv.h[1] = __floats2half2_rn(vf.z, vf.w);
    uint2* base = (uint2*)g_kv + (size_t)n * 256;
    base[off]       = pk.u;
    base[off + 128] = pv.u;
}

__global__ __launch_bounds__(256)
void l1attn_sparse_kernel(const float* __restrict__ q,
                          const int*   __restrict__ coo,
                          float*       __restrict__ out)
{
    const int tp   = blockIdx.x;       // token pair
    const int b    = blockIdx.y;       // batch
    const int tid  = threadIdx.x;      // 0..255
    const int h    = tid >> 5;         // warp = head
    const int lane = tid & 31;
    const int qt   = lane >> 3;        // edge quarter (0..3)
    const int c    = lane & 7;         // 8-col (16B) chunk within head row

    const int tA = 2 * tp;
    const int tB = tA + 1;

    // per-lane coo src for both tokens
    const int dstA = __ldg(&coo[3 * (tA * DEG)]);
    const int dstB = __ldg(&coo[3 * (tB * DEG)]);
    const int offA = __ldg(&coo[3 * (tA * DEG + lane) + 1]) * U4TOK;
    const int offB = __ldg(&coo[3 * (tB * DEG + lane) + 1]) * U4TOK;

    // q chunks for both tokens -> 4 half2 registers each
    const size_t qbaseA = ((size_t)(b * NTOK + dstA)) * ROW;
    const size_t qbaseB = ((size_t)(b * NTOK + dstB)) * ROW;
    const float4 qa0 = *(const float4*)(q + qbaseA + h * WID + 8 * c);
    const float4 qa1 = *(const float4*)(q + qbaseA + h * WID + 8 * c + 4);
    const float4 qb0 = *(const float4*)(q + qbaseB + h * WID + 8 * c);
    const float4 qb1 = *(const float4*)(q + qbaseB + h * WID + 8 * c + 4);
    const __half2 qhA0 = __floats2half2_rn(qa0.x, qa0.y);
    const __half2 qhA1 = __floats2half2_rn(qa0.z, qa0.w);
    const __half2 qhA2 = __floats2half2_rn(qa1.x, qa1.y);
    const __half2 qhA3 = __floats2half2_rn(qa1.z, qa1.w);
    const __half2 qhB0 = __floats2half2_rn(qb0.x, qb0.y);
    const __half2 qhB1 = __floats2half2_rn(qb0.z, qb0.w);
    const __half2 qhB2 = __floats2half2_rn(qb1.x, qb1.y);
    const __half2 qhB3 = __floats2half2_rn(qb1.z, qb1.w);

    const uint4* kvbase = (const uint4*)g_kv + (size_t)(b * NTOK) * U4TOK + h * 8 + c;

    // edge offsets for this lane's quarter (edges 4i+qt), via shuffle
    int koffA[8], koffB[8];
#pragma unroll
    for (int i = 0; i < 8; ++i) {
        koffA[i] = __shfl_sync(0xFFFFFFFFu, offA, 4 * i + qt);
        koffB[i] = __shfl_sync(0xFFFFFFFFu, offB, 4 * i + qt);
    }

    // ---- Phase 2: both tokens interleaved, 4 edges per warp-load ----
    float dA[8], dB[8];
#pragma unroll
    for (int i = 0; i < 8; ++i) {
        const uint4 krA = kvbase[koffA[i]];
        const uint4 krB = kvbase[koffB[i]];
        {
            const __half2 d0 = __habs2(__hsub2(qhA0, *(const __half2*)&krA.x));
            const __half2 d1 = __habs2(__hsub2(qhA1, *(const __half2*)&krA.y));
            const __half2 d2 = __habs2(__hsub2(qhA2, *(const __half2*)&krA.z));
            const __half2 d3 = __habs2(__hsub2(qhA3, *(const __half2*)&krA.w));
            const __half2 s01 = __hadd2(d0, d1);
            const __half2 s23 = __hadd2(d2, d3);
            const float2 f0 = __half22float2(s01);
            const float2 f1 = __half22float2(s23);
            const float2 fs = unpack2(add2(pack2(f0.x, f0.y), pack2(f1.x, f1.y)));
            dA[i] = fs.x + fs.y;
        }
        {
            const __half2 d0 = __habs2(__hsub2(qhB0, *(const __half2*)&krB.x));
            const __half2 d1 = __habs2(__hsub2(qhB1, *(const __half2*)&krB.y));
            const __half2 d2 = __habs2(__hsub2(qhB2, *(const __half2*)&krB.z));
            const __half2 d3 = __habs2(__hsub2(qhB3, *(const __half2*)&krB.w));
            const __half2 s01 = __hadd2(d0, d1);
            const __half2 s23 = __hadd2(d2, d3);
            const float2 f0 = __half22float2(s01);
            const float2 f1 = __half22float2(s23);
            const float2 fs = unpack2(add2(pack2(f0.x, f0.y), pack2(f1.x, f1.y)));
            dB[i] = fs.x + fs.y;
        }
    }

    // ---- multi-reduce within each 8-lane group, A/B interleaved ----
#pragma unroll
    for (int o = 4; o >= 1; o >>= 1) {
        const bool hi = (lane & o) != 0;
#pragma unroll
        for (int i = 0; i < o; ++i) {
            const float keepA = hi ? dA[i + o] : dA[i];
            const float sendA = hi ? dA[i]     : dA[i + o];
            const float keepB = hi ? dB[i + o] : dB[i];
            const float sendB = hi ? dB[i]     : dB[i + o];
            dA[i] = keepA + __shfl_xor_sync(0xFFFFFFFFu, sendA, o);
            dB[i] = keepB + __shfl_xor_sync(0xFFFFFFFFu, sendB, o);
        }
    }

    // ---- Phase 3: softmax (no max-subtract), A/B interleaved ----
    const float eA = __expf(dA[0] * SCALE);
    const float eB = __expf(dB[0] * SCALE);
    float sA = eA, sB = eB;
#pragma unroll
    for (int o = 16; o > 0; o >>= 1) {
        sA += __shfl_xor_sync(0xFFFFFFFFu, sA, o);
        sB += __shfl_xor_sync(0xFFFFFFFFu, sB, o);
    }
    const float wgtA = eA * __fdividef(1.0f, sA);
    const float wgtB = eB * __fdividef(1.0f, sB);

    // packed half2 weights for edges 4i+qt
    __half2 whA[8], whB[8];
#pragma unroll
    for (int i = 0; i < 8; ++i) {
        whA[i] = __float2half2_rn(__shfl_sync(0xFFFFFFFFu, wgtA, i | (lane & 24)));
        whB[i] = __float2half2_rn(__shfl_sync(0xFFFFFFFFu, wgtB, i | (lane & 24)));
    }

    // ---- Phase 4: HFMA2 accumulation, even/odd split, A/B interleaved ----
    const __half2 hz = __float2half2_rn(0.f);
    __half2 aE[4] = {hz, hz, hz, hz}, aO[4] = {hz, hz, hz, hz};
    __half2 bE[4] = {hz, hz, hz, hz}, bO[4] = {hz, hz, hz, hz};
#pragma unroll
    for (int i = 0; i < 8; i += 2) {
        const uint4 vAe = kvbase[koffA[i] + 64];
        const uint4 vAo = kvbase[koffA[i + 1] + 64];
        const uint4 vBe = kvbase[koffB[i] + 64];
        const uint4 vBo = kvbase[koffB[i + 1] + 64];
        aE[0] = __hfma2(*(const __half2*)&vAe.x, whA[i], aE[0]);
        aE[1] = __hfma2(*(const __half2*)&vAe.y, whA[i], aE[1]);
        aE[2] = __hfma2(*(const __half2*)&vAe.z, whA[i], aE[2]);
        aE[3] = __hfma2(*(const __half2*)&vAe.w, whA[i], aE[3]);
        aO[0] = __hfma2(*(const __half2*)&vAo.x, whA[i + 1], aO[0]);
        aO[1] = __hfma2(*(const __half2*)&vAo.y, whA[i + 1], aO[1]);
        aO[2] = __hfma2(*(const __half2*)&vAo.z, whA[i + 1], aO[2]);
        aO[3] = __hfma2(*(const __half2*)&vAo.w, whA[i + 1], aO[3]);
        bE[0] = __hfma2(*(const __half2*)&vBe.x, whB[i], bE[0]);
        bE[1] = __hfma2(*(const __half2*)&vBe.y, whB[i], bE[1]);
        bE[2] = __hfma2(*(const __half2*)&vBe.z, whB[i], bE[2]);
        bE[3] = __hfma2(*(const __half2*)&vBe.w, whB[i], bE[3]);
        bO[0] = __hfma2(*(const __half2*)&vBo.x, whB[i + 1], bO[0]);
        bO[1] = __hfma2(*(const __half2*)&vBo.y, whB[i + 1], bO[1]);
        bO[2] = __hfma2(*(const __half2*)&vBo.z, whB[i + 1], bO[2]);
        bO[3] = __hfma2(*(const __half2*)&vBo.w, whB[i + 1], bO[3]);
    }

    // combine even/odd partials in fp32 (packed), both tokens
    u64 accA[4], accB[4];
#pragma unroll
    for (int i = 0; i < 4; ++i) {
        const float2 ea = __half22float2(aE[i]), oa = __half22float2(aO[i]);
        const float2 eb = __half22float2(bE[i]), ob = __half22float2(bO[i]);
        accA[i] = add2(pack2(ea.x, ea.y), pack2(oa.x, oa.y));
        accB[i] = add2(pack2(eb.x, eb.y), pack2(ob.x, ob.y));
    }

    // ---- epilogue multi-reduce across quarters (bits 3,4), packed, A/B ----
    const bool b3 = (lane & 8)  != 0;
    const bool b4 = (lane & 16) != 0;
    {
        const u64 kA0 = b3 ? accA[2] : accA[0], sA0 = b3 ? accA[0] : accA[2];
        const u64 kA1 = b3 ? accA[3] : accA[1], sA1 = b3 ? accA[1] : accA[3];
        const u64 kB0 = b3 ? accB[2] : accB[0], sB0 = b3 ? accB[0] : accB[2];
        const u64 kB1 = b3 ? accB[3] : accB[1], sB1 = b3 ? accB[1] : accB[3];
        const float2 fa0 = unpack2(sA0), fa1 = unpack2(sA1);
        const float2 fb0 = unpack2(sB0), fb1 = unpack2(sB1);
        accA[0] = add2(kA0, pack2(__shfl_xor_sync(0xFFFFFFFFu, fa0.x, 8),
                                  __shfl_xor_sync(0xFFFFFFFFu, fa0.y, 8)));
        accA[1] = add2(kA1, pack2(__shfl_xor_sync(0xFFFFFFFFu, fa1.x, 8),
                                  __shfl_xor_sync(0xFFFFFFFFu, fa1.y, 8)));
        accB[0] = add2(kB0, pack2(__shfl_xor_sync(0xFFFFFFFFu, fb0.x, 8),
                                  __shfl_xor_sync(0xFFFFFFFFu, fb0.y, 8)));
        accB[1] = add2(kB1, pack2(__shfl_xor_sync(0xFFFFFFFFu, fb1.x, 8),
                                  __shfl_xor_sync(0xFFFFFFFFu, fb1.y, 8)));
    }
    {
        const u64 kA = b4 ? accA[1] : accA[0], sA0 = b4 ? accA[0] : accA[1];
        const u64 kB = b4 ? accB[1] : accB[0], sB0 = b4 ? accB[0] : accB[1];
        const float2 fa = unpack2(sA0), fb = unpack2(sB0);
        accA[0] = add2(kA, pack2(__shfl_xor_sync(0xFFFFFFFFu, fa.x, 16),
                                 __shfl_xor_sync(0xFFFFFFFFu, fa.y, 16)));
        accB[0] = add2(kB, pack2(__shfl_xor_sync(0xFFFFFFFFu, fb.x, 16),
                                 __shfl_xor_sync(0xFFFFFFFFu, fb.y, 16)));
    }

    // lane owns output cols 8c + 4*b3 + 2*b4 + {0,1} for both tokens
    const int ocol = 8 * c + (b3 ? 4 : 0) + (b4 ? 2 : 0);
    const float2 rA = unpack2(accA[0]);
    const float2 rB = unpack2(accB[0]);
    *(float2*)(out + qbaseA + h * WID + ocol) = rA;
    *(float2*)(out + qbaseB + h * WID + ocol) = rB;
}

extern "C" void kernel_launch(void* const* d_in, const int* in_sizes, int n_in,
                              void* d_out, int out_size)
{
    const float* q   = (const float*)d_in[0];
    const float* k   = (const float*)d_in[1];
    const float* v   = (const float*)d_in[2];
    const int*   coo = (const int*)d_in[3];
    float*       out = (float*)d_out;

    convert_kernel<<<TOT / 4 / 256, 256>>>(k, v);
    dim3 grid(NTOK / 2, BS);
    l1attn_sparse_kernel<<<grid, 256>>>(q, coo, out);
}

// round 12
// speedup vs baseline: 1.0708x; 1.0708x over previous
#include <cuda_runtime.h>
#include <cuda_fp16.h>

// L1AttnSparse — GB300 sm_103a, round 12: R9 structure + v-row prefetch
// overlapping the softmax chain (redux removed: not supported on sm_103).
// bs=2, n_tok=2048, n_heads=8, width=64, deg=32
// Warp = head; 8 lanes per edge; interleaved fp16 KV staging buffer
// (k at [0], v at +1024B). HFMA2 phase-4 accumulation with even/odd split.

#define BS   2
#define NTOK 2048
#define NH   8
#define WID  64
#define DEG  32
#define ROW  (NH * WID)            // 512 floats per token row
#define TOT  (BS * NTOK * ROW)     // 2,097,152 elements per tensor
#define U4TOK 128                  // uint4 per interleaved token row (2048B)
#define SCALE (-0.125f)            // -1/sqrt(64)

typedef unsigned long long u64;

// interleaved: token n -> [n*2048, +1024) = k row fp16, [+1024, +2048) = v row
__device__ __half2 g_kv[TOT];      // 8MB

__device__ __forceinline__ u64 pack2(float lo, float hi) {
    u64 r;
    asm("mov.b64 %0, {%1, %2};" : "=l"(r) : "f"(lo), "f"(hi));
    return r;
}
__device__ __forceinline__ float2 unpack2(u64 p) {
    float2 f;
    asm("mov.b64 {%0, %1}, %2;" : "=f"(f.x), "=f"(f.y) : "l"(p));
    return f;
}
__device__ __forceinline__ u64 add2(u64 a, u64 b) {
    u64 r;
    asm("add.rn.f32x2 %0, %1, %2;" : "=l"(r) : "l"(a), "l"(b));
    return r;
}

__global__ __launch_bounds__(256)
void convert_kernel(const float* __restrict__ k, const float* __restrict__ v)
{
    const int i = blockIdx.x * blockDim.x + threadIdx.x;   // one float4 of k and v
    const int n   = i >> 7;            // token
    const int off = i & 127;           // uint2 slot within row
    const float4 kf = ((const float4*)k)[i];
    const float4 vf = ((const float4*)v)[i];
    union { __half2 h[2]; uint2 u; } pk, pv;
    pk.h[0] = __floats2half2_rn(kf.x, kf.y);
    pk.h[1] = __floats2half2_rn(kf.z, kf.w);
    pv.h[0] = __floats2half2_rn(vf.x, vf.y);
    pv.h[1] = __floats2half2_rn(vf.z, vf.w);
    uint2* base = (uint2*)g_kv + (size_t)n * 256;
    base[off]       = pk.u;
    base[off + 128] = pv.u;
}

__global__ __launch_bounds__(256)
void l1attn_sparse_kernel(const float* __restrict__ q,
                          const int*   __restrict__ coo,
                          float*       __restrict__ out)
{
    const int t    = blockIdx.x;       // token
    const int b    = blockIdx.y;       // batch
    const int tid  = threadIdx.x;      // 0..255
    const int h    = tid >> 5;         // warp = head
    const int lane = tid & 31;
    const int qt   = lane >> 3;        // edge quarter (0..3)
    const int c    = lane & 7;         // 8-col (16B) chunk within head row

    // per-lane coo src (L1 hits across warps), kept in register
    const int dst   = __ldg(&coo[3 * (t * DEG)]);
    const int myoff = __ldg(&coo[3 * (t * DEG + lane) + 1]) * U4TOK;

    // q chunk (8 cols) -> 4 half2 registers
    const size_t qbase = ((size_t)(b * NTOK + dst)) * ROW;
    const float4 qa = *(const float4*)(q + qbase + h * WID + 8 * c);
    const float4 qb = *(const float4*)(q + qbase + h * WID + 8 * c + 4);
    const __half2 qh0 = __floats2half2_rn(qa.x, qa.y);
    const __half2 qh1 = __floats2half2_rn(qa.z, qa.w);
    const __half2 qh2 = __floats2half2_rn(qb.x, qb.y);
    const __half2 qh3 = __floats2half2_rn(qb.z, qb.w);

    const uint4* kvbase = (const uint4*)g_kv + (size_t)(b * NTOK) * U4TOK + h * 8 + c;

    // edge offsets for this lane's quarter (edges 4i+qt), via shuffle
    int koff[8];
#pragma unroll
    for (int i = 0; i < 8; ++i)
        koff[i] = __shfl_sync(0xFFFFFFFFu, myoff, 4 * i + qt);

    // ---- Phase 2: 8 iterations, 4 edges per warp-load ----
    float d[8];
#pragma unroll
    for (int i = 0; i < 8; ++i) {
        const uint4 kr = kvbase[koff[i]];
        const __half2 d0 = __habs2(__hsub2(qh0, *(const __half2*)&kr.x));
        const __half2 d1 = __habs2(__hsub2(qh1, *(const __half2*)&kr.y));
        const __half2 d2 = __habs2(__hsub2(qh2, *(const __half2*)&kr.z));
        const __half2 d3 = __habs2(__hsub2(qh3, *(const __half2*)&kr.w));
        const __half2 s01 = __hadd2(d0, d1);           // one fp16 add level
        const __half2 s23 = __hadd2(d2, d3);
        const float2 f0 = __half22float2(s01);
        const float2 f1 = __half22float2(s23);
        const float2 fs = unpack2(add2(pack2(f0.x, f0.y), pack2(f1.x, f1.y)));
        d[i] = fs.x + fs.y;
    }

    // ---- multi-reduce d[8] within each 8-lane group (7 shuffles) ----
    // lane ends holding the full score of edge  e(lane) = 4*(lane&7) + (lane>>3)
#pragma unroll
    for (int o = 4; o >= 1; o >>= 1) {
        const bool hi = (lane & o) != 0;
#pragma unroll
        for (int i = 0; i < o; ++i) {
            const float keep = hi ? d[i + o] : d[i];
            const float send = hi ? d[i]     : d[i + o];
            d[i] = keep + __shfl_xor_sync(0xFFFFFFFFu, send, o);
        }
    }

    // ---- prefetch v rows NOW: in flight during softmax + weight shuffles ----
    uint4 vr[8];
#pragma unroll
    for (int i = 0; i < 8; ++i)
        vr[i] = kvbase[koff[i] + 64];

    // ---- Phase 3: softmax, no max subtraction (scores bounded, fp32 safe) ----
    const float e = __expf(d[0] * SCALE);
    float s = e;
#pragma unroll
    for (int o = 16; o > 0; o >>= 1)
        s += __shfl_xor_sync(0xFFFFFFFFu, s, o);
    const float wgt = e * __fdividef(1.0f, s);

    // weights for edges 4i+qt as half2 (lane i | (lane & 24))
    __half2 wh[8];
#pragma unroll
    for (int i = 0; i < 8; ++i)
        wh[i] = __float2half2_rn(__shfl_sync(0xFFFFFFFFu, wgt, i | (lane & 24)));

    // ---- Phase 4: HFMA2 accumulation, even/odd edge split for precision ----
    const __half2 hz = __float2half2_rn(0.f);
    __half2 aE0 = hz, aE1 = hz, aE2 = hz, aE3 = hz;
    __half2 aO0 = hz, aO1 = hz, aO2 = hz, aO3 = hz;
#pragma unroll
    for (int i = 0; i < 8; i += 2) {
        const uint4 ve = vr[i];
        aE0 = __hfma2(*(const __half2*)&ve.x, wh[i], aE0);
        aE1 = __hfma2(*(const __half2*)&ve.y, wh[i], aE1);
        aE2 = __hfma2(*(const __half2*)&ve.z, wh[i], aE2);
        aE3 = __hfma2(*(const __half2*)&ve.w, wh[i], aE3);
        const uint4 vo = vr[i + 1];
        aO0 = __hfma2(*(const __half2*)&vo.x, wh[i + 1], aO0);
        aO1 = __hfma2(*(const __half2*)&vo.y, wh[i + 1], aO1);
        aO2 = __hfma2(*(const __half2*)&vo.z, wh[i + 1], aO2);
        aO3 = __hfma2(*(const __half2*)&vo.w, wh[i + 1], aO3);
    }

    // combine even/odd partials in fp32 (packed)
    u64 acc0, acc1, acc2, acc3;
    {
        const float2 e0 = __half22float2(aE0), o0 = __half22float2(aO0);
        const float2 e1 = __half22float2(aE1), o1 = __half22float2(aO1);
        const float2 e2 = __half22float2(aE2), o2 = __half22float2(aO2);
        const float2 e3 = __half22float2(aE3), o3 = __half22float2(aO3);
        acc0 = add2(pack2(e0.x, e0.y), pack2(o0.x, o0.y));
        acc1 = add2(pack2(e1.x, e1.y), pack2(o1.x, o1.y));
        acc2 = add2(pack2(e2.x, e2.y), pack2(o2.x, o2.y));
        acc3 = add2(pack2(e3.x, e3.y), pack2(o3.x, o3.y));
    }

    // ---- epilogue multi-reduce across quarters (bits 3,4), packed ----
    const bool b3 = (lane & 8)  != 0;
    const bool b4 = (lane & 16) != 0;
    {
        const u64 keepA = b3 ? acc2 : acc0;
        const u64 sendA = b3 ? acc0 : acc2;
        const u64 keepB = b3 ? acc3 : acc1;
        const u64 sendB = b3 ? acc1 : acc3;
        const float2 sa = unpack2(sendA);
        const float2 sb = unpack2(sendB);
        const u64 shA = pack2(__shfl_xor_sync(0xFFFFFFFFu, sa.x, 8),
                              __shfl_xor_sync(0xFFFFFFFFu, sa.y, 8));
        const u64 shB = pack2(__shfl_xor_sync(0xFFFFFFFFu, sb.x, 8),
                              __shfl_xor_sync(0xFFFFFFFFu, sb.y, 8));
        acc0 = add2(keepA, shA);
        acc1 = add2(keepB, shB);
    }
    {
        const u64 keep = b4 ? acc1 : acc0;
        const u64 send = b4 ? acc0 : acc1;
        const float2 sv = unpack2(send);
        const u64 sh = pack2(__shfl_xor_sync(0xFFFFFFFFu, sv.x, 16),
                             __shfl_xor_sync(0xFFFFFFFFu, sv.y, 16));
        acc0 = add2(keep, sh);
    }

    // lane owns output cols 8c + 4*b3 + 2*b4 + {0,1}
    const int ocol = 8 * c + (b3 ? 4 : 0) + (b4 ? 2 : 0);
    const float2 res = unpack2(acc0);
    *(float2*)(out + qbase + h * WID + ocol) = res;
}

extern "C" void kernel_launch(void* const* d_in, const int* in_sizes, int n_in,
                              void* d_out, int out_size)
{
    const float* q   = (const float*)d_in[0];
    const float* k   = (const float*)d_in[1];
    const float* v   = (const float*)d_in[2];
    const int*   coo = (const int*)d_in[3];
    float*       out = (float*)d_out;

    convert_kernel<<<TOT / 4 / 256, 256>>>(k, v);
    dim3 grid(NTOK, BS);
    l1attn_sparse_kernel<<<grid, 256>>>(q, coo, out);
}